// round 2
// baseline (speedup 1.0000x reference)
#include <cuda_runtime.h>

#define BATCH 64
#define KPTS  2048
#define NTHR  128
#define RI    4
#define TI    (NTHR * RI)          // 512 query points per block
#define NI    (KPTS / TI)          // 4 i-chunks
#define NBLK  (NI * 2 * BATCH)     // 512 blocks
#define INF_BITS 0x7f800000

typedef unsigned long long ull;

__device__ float g_part[NBLK];

// ---------- f32x2 packed helpers ----------
__device__ __forceinline__ ull pk(float a, float b) {
    ull r; asm("mov.b64 %0, {%1,%2};" : "=l"(r) : "f"(a), "f"(b)); return r;
}
__device__ __forceinline__ void upk(ull v, float& a, float& b) {
    asm("mov.b64 {%0,%1}, %2;" : "=f"(a), "=f"(b) : "l"(v));
}
__device__ __forceinline__ ull fma2(ull a, ull b, ull c) {
    ull d; asm("fma.rn.f32x2 %0, %1, %2, %3;" : "=l"(d) : "l"(a), "l"(b), "l"(c)); return d;
}

// ---------- main: one pass per direction (blockIdx.y selects) ----------
// For each query point a_i (registers), min over ALL tile points b_j (smem,
// broadcast reads). d2 = a2 + (b2 - 2ax*bx - 2ay*by); min folds a2 at the end.
// Block finishes its 512 query points completely -> sqrt -> block-sum partial.
__global__ void __launch_bounds__(NTHR)
chamfer_pass(const float* __restrict__ P, const float* __restrict__ T) {
    __shared__ ulonglong2 sA[KPTS];   // {(-2bx,-2bx),(-2by,-2by)}  32 KB
    __shared__ ull        sB[KPTS];   // {b2,b2}                    16 KB

    const int dir = blockIdx.y;            // 0: query=P tile=T ; 1: swapped
    const int b   = blockIdx.z;
    const int tid = threadIdx.x;

    const float* Ap = (dir ? T : P) + b * (2 * KPTS);  // query side
    const float* Bp = (dir ? P : T) + b * (2 * KPTS);  // tile side

    // stage full tile (2048 points, coalesced)
    for (int t = tid; t < KPTS; t += NTHR) {
        float bx = Bp[t];
        float by = Bp[KPTS + t];
        float m2x = -2.0f * bx, m2y = -2.0f * by;
        sA[t] = make_ulonglong2(pk(m2x, m2x), pk(m2y, m2y));
        float b2 = bx * bx + by * by;
        sB[t] = pk(b2, b2);
    }

    // query points: 4 consecutive i per thread, vectorized load
    const int i0 = blockIdx.x * TI + tid * RI;
    float4 x4 = *reinterpret_cast<const float4*>(Ap + i0);
    float4 y4 = *reinterpret_cast<const float4*>(Ap + KPTS + i0);
    ull px01 = pk(x4.x, x4.y), px23 = pk(x4.z, x4.w);
    ull py01 = pk(y4.x, y4.y), py23 = pk(y4.z, y4.w);

    const float FINF = __int_as_float(INF_BITS);
    float r0 = FINF, r1 = FINF, r2 = FINF, r3 = FINF;

    __syncthreads();

#pragma unroll 16
    for (int j = 0; j < KPTS; ++j) {
        ulonglong2 Aj = sA[j];     // broadcast LDS.128
        ull        c2 = sB[j];     // broadcast LDS.64

        ull v0 = fma2(py01, Aj.y, fma2(px01, Aj.x, c2));
        ull v1 = fma2(py23, Aj.y, fma2(px23, Aj.x, c2));

        float a, bb, c, d;
        upk(v0, a, bb); upk(v1, c, d);
        r0 = fminf(r0, a); r1 = fminf(r1, bb);
        r2 = fminf(r2, c); r3 = fminf(r3, d);
    }

    // fold a2, clamp, sqrt, per-thread partial
    float p2a = x4.x * x4.x + y4.x * y4.x;
    float p2b = x4.y * x4.y + y4.y * y4.y;
    float p2c = x4.z * x4.z + y4.z * y4.z;
    float p2d = x4.w * x4.w + y4.w * y4.w;
    float s = sqrtf(fmaxf(p2a + r0, 0.0f))
            + sqrtf(fmaxf(p2b + r1, 0.0f))
            + sqrtf(fmaxf(p2c + r2, 0.0f))
            + sqrtf(fmaxf(p2d + r3, 0.0f));

    // deterministic block reduction (reuse dead tile smem)
    __syncthreads();
    float* ss = reinterpret_cast<float*>(sA);
    ss[tid] = s;
    __syncthreads();
#pragma unroll
    for (int st = NTHR / 2; st > 0; st >>= 1) {
        if (tid < st) ss[tid] += ss[tid + st];
        __syncthreads();
    }
    if (tid == 0) {
        int bid = blockIdx.x + NI * (blockIdx.y + 2 * blockIdx.z);
        g_part[bid] = ss[0];
    }
}

// ---------- final deterministic sum of 512 partials ----------
__global__ void reduce_final(float* out) {
    __shared__ float ss[256];
    ss[threadIdx.x] = g_part[threadIdx.x] + g_part[threadIdx.x + 256];
    __syncthreads();
#pragma unroll
    for (int st = 128; st > 0; st >>= 1) {
        if (threadIdx.x < st) ss[threadIdx.x] += ss[threadIdx.x + st];
        __syncthreads();
    }
    if (threadIdx.x == 0)
        out[0] = ss[0] * (1.0f / (float)(BATCH * KPTS));
}

extern "C" void kernel_launch(void* const* d_in, const int* in_sizes, int n_in,
                              void* d_out, int out_size) {
    const float* P = (const float*)d_in[0];   // predicted (64, 4096)
    const float* T = (const float*)d_in[1];   // target    (64, 4096)
    (void)in_sizes; (void)n_in; (void)out_size;

    dim3 grid(NI, 2, BATCH);                  // 4 x 2 x 64 = 512 blocks
    chamfer_pass<<<grid, NTHR>>>(P, T);
    reduce_final<<<1, 256>>>((float*)d_out);
}